// round 2
// baseline (speedup 1.0000x reference)
#include <cuda_runtime.h>
#include <math.h>

// ---------------- problem constants ----------------
#define NLOC   4096
#define NALL   6144
#define NEDGE  262144
#define NANGLE 409600
#define NDIM   128
#define EDIM   64
#define ADIM   32
// dyn_e_sel = 64/10 = 6.4 ; dyn_a_sel = 10/10 = 1.0

// ---------------- scratch (device globals; no allocation allowed) ----------------
__device__ float g_edge_upd[(size_t)NEDGE * NDIM];   // act(edge_info@Wne+b)*sw, per edge (134MB)
__device__ float g_reduced [(size_t)NEDGE * EDIM];   // segment_sum of edge_angle*a_sw (67MB)
__device__ int   g_count [NLOC];
__device__ int   g_off   [NLOC + 1];
__device__ int   g_cursor[NLOC];
__device__ int   g_ebn   [NEDGE];                    // edge ids grouped by n2e (CSR)

__device__ __forceinline__ float silu_f(float x) {
    return x * (1.0f / (1.0f + __expf(-x)));
}

// ---------------- small helper kernels ----------------
__global__ void k_zero() {
    int i = blockIdx.x * blockDim.x + threadIdx.x;
    int stride = gridDim.x * blockDim.x;
    float4 z = make_float4(0.f, 0.f, 0.f, 0.f);
    float4* r = (float4*)g_reduced;
    const int n4 = NEDGE * EDIM / 4;
    for (int j = i; j < n4; j += stride) r[j] = z;
    for (int j = i; j < NLOC; j += stride) { g_count[j] = 0; g_cursor[j] = 0; }
}

__global__ void k_hist(const int* __restrict__ n2e) {
    int i = blockIdx.x * blockDim.x + threadIdx.x;
    if (i < NEDGE) atomicAdd(&g_count[n2e[i]], 1);
}

__global__ void k_scan() {
    __shared__ int ss[1024];
    int t = threadIdx.x;
    int c0 = g_count[t * 4 + 0];
    int c1 = g_count[t * 4 + 1];
    int c2 = g_count[t * 4 + 2];
    int c3 = g_count[t * 4 + 3];
    int p1 = c0, p2 = p1 + c1, p3 = p2 + c2, s = p3 + c3;
    ss[t] = s;
    __syncthreads();
    for (int d = 1; d < 1024; d <<= 1) {
        int v = (t >= d) ? ss[t - d] : 0;
        __syncthreads();
        ss[t] += v;
        __syncthreads();
    }
    int base = (t > 0) ? ss[t - 1] : 0;
    g_off[t * 4 + 0] = base;
    g_off[t * 4 + 1] = base + p1;
    g_off[t * 4 + 2] = base + p2;
    g_off[t * 4 + 3] = base + p3;
    if (t == 1023) g_off[NLOC] = ss[1023];
}

__global__ void k_scatter(const int* __restrict__ n2e) {
    int i = blockIdx.x * blockDim.x + threadIdx.x;
    if (i < NEDGE) {
        int n = n2e[i];
        int p = atomicAdd(&g_cursor[n], 1);
        g_ebn[g_off[n] + p] = i;
    }
}

// ---------------- edge kernel: fused dual GEMM over edge_info ----------------
// 64 edges/block, 256 threads, K=320, NOUT=192 (cols 0..127 -> W_node_edge, 128..191 -> W_edge_self)
#define E_PAD 324
__global__ void __launch_bounds__(256, 2) k_edge(
    const float* __restrict__ node_ext, const float* __restrict__ edge_ebd,
    const float* __restrict__ sw,
    const int* __restrict__ n2e, const int* __restrict__ nx2e,
    const float* __restrict__ Wne, const float* __restrict__ bne,
    const float* __restrict__ Wes, const float* __restrict__ bes,
    const float* __restrict__ eres0, float* __restrict__ e_out)
{
    extern __shared__ float sm[];
    float* info = sm;                 // [64][E_PAD]
    float* wt   = sm + 64 * E_PAD;    // [16][192]
    const int tid = threadIdx.x;
    const int lane = tid & 31, warp = tid >> 5;
    const int e0 = blockIdx.x * 64;

    // gather edge_info = [node_i(128) | nei_node(128) | edge_ebd(64)]
    #pragma unroll
    for (int i = 0; i < 8; i++) {
        int el = warp * 8 + i;
        int e = e0 + el;
        int ni = n2e[e], nx = nx2e[e];
        const float4* pn = (const float4*)(node_ext + (size_t)ni * NDIM);
        const float4* px = (const float4*)(node_ext + (size_t)nx * NDIM);
        const float4* pe = (const float4*)(edge_ebd + (size_t)e  * EDIM);
        for (int c = lane; c < 80; c += 32) {
            float4 v;
            if (c < 32)      v = pn[c];
            else if (c < 64) v = px[c - 32];
            else             v = pe[c - 64];
            *(float4*)(info + el * E_PAD + c * 4) = v;
        }
    }

    const int tx = tid & 31, ty = tid >> 5;   // cols tx*6.. , edges ty*8..
    float acc[8][6];
    #pragma unroll
    for (int i = 0; i < 8; i++)
        #pragma unroll
        for (int j = 0; j < 6; j++) acc[i][j] = 0.f;

    for (int k0 = 0; k0 < 320; k0 += 16) {
        __syncthreads();
        #pragma unroll
        for (int i = 0; i < 12; i++) {
            int idx = i * 256 + tid;
            int kk = idx / 192, c = idx - kk * 192;
            float v = (c < 128) ? Wne[(size_t)(k0 + kk) * 128 + c]
                                : Wes[(size_t)(k0 + kk) * 64 + (c - 128)];
            wt[kk * 192 + c] = v;
        }
        __syncthreads();
        #pragma unroll
        for (int kk = 0; kk < 16; kk++) {
            float a[8], w[6];
            #pragma unroll
            for (int i = 0; i < 8; i++) a[i] = info[(ty * 8 + i) * E_PAD + k0 + kk];
            #pragma unroll
            for (int j = 0; j < 6; j++) w[j] = wt[kk * 192 + tx * 6 + j];
            #pragma unroll
            for (int i = 0; i < 8; i++)
                #pragma unroll
                for (int j = 0; j < 6; j++) acc[i][j] += a[i] * w[j];
        }
    }

    #pragma unroll
    for (int i = 0; i < 8; i++) {
        int el = ty * 8 + i;
        int e = e0 + el;
        float swv = sw[e];
        #pragma unroll
        for (int j = 0; j < 6; j++) {
            int c = tx * 6 + j;
            float x = acc[i][j];
            if (c < 128) {
                float y = silu_f(x + bne[c]);
                g_edge_upd[(size_t)e * 128 + c] = y * swv;
            } else {
                int cc = c - 128;
                float y = silu_f(x + bes[cc]);
                e_out[(size_t)e * 64 + cc] = edge_ebd[(size_t)e * 64 + cc] + eres0[cc] * y;
            }
        }
    }
}

// ---------------- angle kernel: fused dual GEMM over angle_info ----------------
// 64 angles/block, 256 threads, K=288, NOUT=96 (cols 0..63 -> W_edge_angle1, 64..95 -> W_angle_self)
#define A_PAD 292
__global__ void __launch_bounds__(256, 2) k_angle(
    const float* __restrict__ angle_ebd, const float* __restrict__ node_ext,
    const float* __restrict__ edge_ebd, const float* __restrict__ a_sw,
    const int* __restrict__ n2a, const int* __restrict__ eij2a, const int* __restrict__ eik2a,
    const float* __restrict__ W1, const float* __restrict__ b1,
    const float* __restrict__ Wa, const float* __restrict__ ba,
    const float* __restrict__ ares0, float* __restrict__ a_out)
{
    extern __shared__ float sm[];
    float* info = sm;                 // [64][A_PAD]
    float* wt   = sm + 64 * A_PAD;    // [16][96]
    const int tid = threadIdx.x;
    const int lane = tid & 31, warp = tid >> 5;
    const int a0 = blockIdx.x * 64;

    // gather angle_info = [angle(32) | node(128) | edge_ik(64) | edge_ij(64)]
    #pragma unroll
    for (int i = 0; i < 8; i++) {
        int al = warp * 8 + i;
        int ang = a0 + al;
        const float4* pa  = (const float4*)(angle_ebd + (size_t)ang * ADIM);
        const float4* pn  = (const float4*)(node_ext + (size_t)n2a[ang] * NDIM);
        const float4* pik = (const float4*)(edge_ebd + (size_t)eik2a[ang] * EDIM);
        const float4* pij = (const float4*)(edge_ebd + (size_t)eij2a[ang] * EDIM);
        for (int c = lane; c < 72; c += 32) {
            float4 v;
            if (c < 8)       v = pa[c];
            else if (c < 40) v = pn[c - 8];
            else if (c < 56) v = pik[c - 40];
            else             v = pij[c - 56];
            *(float4*)(info + al * A_PAD + c * 4) = v;
        }
    }

    const int tx = tid & 31, ty = tid >> 5;   // cols tx*3.., angles ty*8..
    float acc[8][3];
    #pragma unroll
    for (int i = 0; i < 8; i++)
        #pragma unroll
        for (int j = 0; j < 3; j++) acc[i][j] = 0.f;

    for (int k0 = 0; k0 < 288; k0 += 16) {
        __syncthreads();
        #pragma unroll
        for (int i = 0; i < 6; i++) {
            int idx = i * 256 + tid;
            int kk = idx / 96, c = idx - kk * 96;
            float v = (c < 64) ? W1[(size_t)(k0 + kk) * 64 + c]
                               : Wa[(size_t)(k0 + kk) * 32 + (c - 64)];
            wt[kk * 96 + c] = v;
        }
        __syncthreads();
        #pragma unroll
        for (int kk = 0; kk < 16; kk++) {
            float a[8], w[3];
            #pragma unroll
            for (int i = 0; i < 8; i++) a[i] = info[(ty * 8 + i) * A_PAD + k0 + kk];
            #pragma unroll
            for (int j = 0; j < 3; j++) w[j] = wt[kk * 96 + tx * 3 + j];
            #pragma unroll
            for (int i = 0; i < 8; i++)
                #pragma unroll
                for (int j = 0; j < 3; j++) acc[i][j] += a[i] * w[j];
        }
    }

    #pragma unroll
    for (int i = 0; i < 8; i++) {
        int al = ty * 8 + i;
        int ang = a0 + al;
        float asw = a_sw[ang];
        int eij = eij2a[ang];
        #pragma unroll
        for (int j = 0; j < 3; j++) {
            int c = tx * 3 + j;
            float x = acc[i][j];
            if (c < 64) {
                float y = silu_f(x + b1[c]) * asw;
                atomicAdd(&g_reduced[(size_t)eij * 64 + c], y);
            } else {
                int cc = c - 64;
                float y = silu_f(x + ba[cc]);
                a_out[(size_t)ang * 32 + cc] = angle_ebd[(size_t)ang * 32 + cc] + ares0[cc] * y;
            }
        }
    }
}

// ---------------- node kernel: CSR reductions + sym + two GEMMs ----------------
__global__ void __launch_bounds__(128) k_node(
    const float* __restrict__ node_ext, const float* __restrict__ edge_ebd,
    const float* __restrict__ sw, const float* __restrict__ h2,
    const int* __restrict__ nx2e,
    const float* __restrict__ Wns, const float* __restrict__ bns,
    const float* __restrict__ Wsym, const float* __restrict__ bsym,
    const float* __restrict__ nr0, const float* __restrict__ nr1, const float* __restrict__ nr2,
    float* __restrict__ n_out)
{
    __shared__ float s_hn[3][128];
    __shared__ float s_he[3][64];
    __shared__ float s_sym[768];
    __shared__ float s_node[128];

    const int n = blockIdx.x;
    const int t = threadIdx.x;
    const int beg = g_off[n], end = g_off[n + 1];

    float hn0 = 0.f, hn1 = 0.f, hn2 = 0.f;
    float he0 = 0.f, he1 = 0.f, he2 = 0.f;
    float msg = 0.f;
    float nodev = node_ext[(size_t)n * 128 + t];
    s_node[t] = nodev;

    // software-pipelined gather loop: prefetch next edge's index chain
    int e_cur = (beg < end) ? g_ebn[beg] : 0;
    int nx_cur = (beg < end) ? nx2e[e_cur] : 0;
    for (int idx = beg; idx < end; idx++) {
        int e = e_cur, nx = nx_cur;
        if (idx + 1 < end) {
            e_cur = g_ebn[idx + 1];
            nx_cur = nx2e[e_cur];
        }
        float swv = sw[e];
        float hx = h2[e * 3 + 0] * swv;
        float hy = h2[e * 3 + 1] * swv;
        float hz = h2[e * 3 + 2] * swv;
        float nv = node_ext[(size_t)nx * 128 + t];
        float mv = g_edge_upd[(size_t)e * 128 + t];
        hn0 += hx * nv; hn1 += hy * nv; hn2 += hz * nv;
        msg += mv;
        if (t < 64) {
            float ev = edge_ebd[(size_t)e * 64 + t];
            he0 += hx * ev; he1 += hy * ev; he2 += hz * ev;
        }
    }

    const float sc = rsqrtf(6.4f);
    s_hn[0][t] = hn0 * sc; s_hn[1][t] = hn1 * sc; s_hn[2][t] = hn2 * sc;
    if (t < 64) { s_he[0][t] = he0 * sc; s_he[1][t] = he1 * sc; s_he[2][t] = he2 * sc; }
    __syncthreads();

    // sym_edge: [a*64+d], sym_node: [256 + a*128+d]  (g = m^T h2g2 / 3)
    #pragma unroll
    for (int a = 0; a < 4; a++) {
        if (t < 64)
            s_sym[a * 64 + t] = (s_he[0][a] * s_he[0][t] + s_he[1][a] * s_he[1][t] +
                                 s_he[2][a] * s_he[2][t]) * (1.f / 3.f);
        s_sym[256 + a * 128 + t] = (s_hn[0][a] * s_hn[0][t] + s_hn[1][a] * s_hn[1][t] +
                                    s_hn[2][a] * s_hn[2][t]) * (1.f / 3.f);
    }
    __syncthreads();

    // node_self: col t of node_row @ Wns(128x128)
    float accS = bns[t];
    #pragma unroll 8
    for (int k = 0; k < 128; k++) accS += s_node[k] * Wns[(size_t)k * 128 + t];

    // node_sym: col t of sym(768) @ Wsym(768x128)
    float accY = bsym[t];
    #pragma unroll 8
    for (int k = 0; k < 768; k++) accY += s_sym[k] * Wsym[(size_t)k * 128 + t];

    float out = nodev + nr0[t] * silu_f(accS) + nr1[t] * silu_f(accY)
              + nr2[t] * (msg * (1.f / 6.4f));
    n_out[(size_t)n * 128 + t] = out;
}

// ---------------- edge2 kernel: reduced(64) @ W_edge_angle2(64x64) ----------------
__global__ void __launch_bounds__(256) k_edge2(
    const float* __restrict__ W2, const float* __restrict__ b2,
    const float* __restrict__ eres1, float* __restrict__ e_out)
{
    __shared__ float w2s[64 * 64];
    __shared__ float in2[64 * 65];
    __shared__ float b2s[64];
    const int tid = threadIdx.x;
    const int e0 = blockIdx.x * 64;

    #pragma unroll
    for (int i = 0; i < 16; i++) {
        int idx = i * 256 + tid;
        w2s[idx] = W2[idx];
    }
    if (tid < 64) b2s[tid] = b2[tid];
    #pragma unroll
    for (int i = 0; i < 16; i++) {
        int idx = i * 256 + tid;
        int e = idx >> 6, k = idx & 63;
        in2[e * 65 + k] = g_reduced[(size_t)(e0 + e) * 64 + k];
    }
    __syncthreads();

    const int tx = tid & 15, ty = tid >> 4;   // cols tx*4.., edges ty*4..
    float acc[4][4];
    #pragma unroll
    for (int i = 0; i < 4; i++)
        #pragma unroll
        for (int j = 0; j < 4; j++) acc[i][j] = 0.f;

    #pragma unroll 4
    for (int k = 0; k < 64; k++) {
        float4 wv = *(const float4*)&w2s[k * 64 + tx * 4];
        float w[4] = { wv.x, wv.y, wv.z, wv.w };
        #pragma unroll
        for (int i = 0; i < 4; i++) {
            float a = in2[(ty * 4 + i) * 65 + k];
            #pragma unroll
            for (int j = 0; j < 4; j++) acc[i][j] += a * w[j];
        }
    }

    #pragma unroll
    for (int i = 0; i < 4; i++) {
        int e = e0 + ty * 4 + i;
        #pragma unroll
        for (int j = 0; j < 4; j++) {
            int c = tx * 4 + j;
            float y = silu_f(acc[i][j] + b2s[c]);
            e_out[(size_t)e * 64 + c] += eres1[c] * y;
        }
    }
}

// ---------------- launch ----------------
extern "C" void kernel_launch(void* const* d_in, const int* in_sizes, int n_in,
                              void* d_out, int out_size)
{
    const float* node_ext  = (const float*)d_in[0];
    const float* edge_ebd  = (const float*)d_in[1];
    const float* h2        = (const float*)d_in[2];
    const float* angle_ebd = (const float*)d_in[3];
    const float* sw        = (const float*)d_in[6];
    const float* a_sw      = (const float*)d_in[9];
    const int*   edge_index  = (const int*)d_in[10];
    const int*   angle_index = (const int*)d_in[11];
    const int* n2e   = edge_index;
    const int* nx2e  = edge_index + NEDGE;
    const int* n2a   = angle_index;
    const int* eij2a = angle_index + NANGLE;
    const int* eik2a = angle_index + 2 * NANGLE;

    const float* Wns  = (const float*)d_in[12];
    const float* bns  = (const float*)d_in[13];
    const float* Wsym = (const float*)d_in[14];
    const float* bsym = (const float*)d_in[15];
    const float* Wne  = (const float*)d_in[16];
    const float* bne  = (const float*)d_in[17];
    const float* Wes  = (const float*)d_in[18];
    const float* bes  = (const float*)d_in[19];
    const float* W1   = (const float*)d_in[20];
    const float* b1   = (const float*)d_in[21];
    const float* W2   = (const float*)d_in[22];
    const float* b2   = (const float*)d_in[23];
    const float* Wa   = (const float*)d_in[24];
    const float* ba   = (const float*)d_in[25];
    const float* nr0  = (const float*)d_in[26];
    const float* nr1  = (const float*)d_in[27];
    const float* nr2  = (const float*)d_in[28];
    const float* er0  = (const float*)d_in[29];
    const float* er1  = (const float*)d_in[30];
    const float* ar0  = (const float*)d_in[31];

    float* out   = (float*)d_out;
    float* n_out = out;
    float* e_out = out + (size_t)NLOC * NDIM;
    float* a_out = out + (size_t)NLOC * NDIM + (size_t)NEDGE * EDIM;

    const int edge_smem  = (64 * E_PAD + 16 * 192) * 4;  // 95232 B
    const int angle_smem = (64 * A_PAD + 16 * 96) * 4;   // 80896 B
    cudaFuncSetAttribute(k_edge,  cudaFuncAttributeMaxDynamicSharedMemorySize, edge_smem);
    cudaFuncSetAttribute(k_angle, cudaFuncAttributeMaxDynamicSharedMemorySize, angle_smem);

    k_zero<<<2048, 256>>>();
    k_hist<<<NEDGE / 256, 256>>>(n2e);
    k_scan<<<1, 1024>>>();
    k_scatter<<<NEDGE / 256, 256>>>(n2e);

    k_edge<<<NEDGE / 64, 256, edge_smem>>>(node_ext, edge_ebd, sw, n2e, nx2e,
                                           Wne, bne, Wes, bes, er0, e_out);
    k_node<<<NLOC, 128>>>(node_ext, edge_ebd, sw, h2, nx2e,
                          Wns, bns, Wsym, bsym, nr0, nr1, nr2, n_out);
    k_angle<<<NANGLE / 64, 256, angle_smem>>>(angle_ebd, node_ext, edge_ebd, a_sw,
                                              n2a, eij2a, eik2a,
                                              W1, b1, Wa, ba, ar0, a_out);
    k_edge2<<<NEDGE / 64, 256>>>(W2, b2, er1, e_out);
}

// round 5
// speedup vs baseline: 1.6353x; 1.6353x over previous
#include <cuda_runtime.h>
#include <math.h>

// ---------------- problem constants ----------------
#define NLOC   4096
#define NALL   6144
#define NEDGE  262144
#define NANGLE 409600
#define NDIM   128
#define EDIM   64
#define ADIM   32
// dyn_e_sel = 64/10 = 6.4 ; dyn_a_sel = 10/10 = 1.0

// ---------------- scratch ----------------
__device__ float g_edge_upd[(size_t)NEDGE * NDIM];
__device__ float g_reduced [(size_t)NEDGE * EDIM];
__device__ int   g_count [NLOC];
__device__ int   g_off   [NLOC + 1];
__device__ int   g_cursor[NLOC];
__device__ int   g_ebn   [NEDGE];

__device__ __forceinline__ float silu_f(float x) {
    return x * (1.0f / (1.0f + __expf(-x)));
}

__device__ __forceinline__ unsigned tf32_bits(float f) {
    unsigned u;
    asm("cvt.rna.tf32.f32 %0, %1;" : "=r"(u) : "f"(f));
    return u;
}

__device__ __forceinline__ void mma_tf32(float* d,
    unsigned a0, unsigned a1, unsigned a2, unsigned a3,
    unsigned b0, unsigned b1)
{
    asm("mma.sync.aligned.m16n8k8.row.col.f32.tf32.tf32.f32 "
        "{%0,%1,%2,%3}, {%4,%5,%6,%7}, {%8,%9}, {%0,%1,%2,%3};"
        : "+f"(d[0]), "+f"(d[1]), "+f"(d[2]), "+f"(d[3])
        : "r"(a0), "r"(a1), "r"(a2), "r"(a3), "r"(b0), "r"(b1));
}

// ---------------- small helper kernels ----------------
__global__ void k_zero() {
    int i = blockIdx.x * blockDim.x + threadIdx.x;
    int stride = gridDim.x * blockDim.x;
    float4 z = make_float4(0.f, 0.f, 0.f, 0.f);
    float4* r = (float4*)g_reduced;
    const int n4 = NEDGE * EDIM / 4;
    for (int j = i; j < n4; j += stride) r[j] = z;
    for (int j = i; j < NLOC; j += stride) { g_count[j] = 0; g_cursor[j] = 0; }
}

__global__ void k_hist(const int* __restrict__ n2e) {
    int i = blockIdx.x * blockDim.x + threadIdx.x;
    if (i < NEDGE) atomicAdd(&g_count[n2e[i]], 1);
}

__global__ void k_scan() {
    __shared__ int ss[1024];
    int t = threadIdx.x;
    int c0 = g_count[t * 4 + 0];
    int c1 = g_count[t * 4 + 1];
    int c2 = g_count[t * 4 + 2];
    int c3 = g_count[t * 4 + 3];
    int p1 = c0, p2 = p1 + c1, p3 = p2 + c2, s = p3 + c3;
    ss[t] = s;
    __syncthreads();
    for (int d = 1; d < 1024; d <<= 1) {
        int v = (t >= d) ? ss[t - d] : 0;
        __syncthreads();
        ss[t] += v;
        __syncthreads();
    }
    int base = (t > 0) ? ss[t - 1] : 0;
    g_off[t * 4 + 0] = base;
    g_off[t * 4 + 1] = base + p1;
    g_off[t * 4 + 2] = base + p2;
    g_off[t * 4 + 3] = base + p3;
    if (t == 1023) g_off[NLOC] = ss[1023];
}

__global__ void k_scatter(const int* __restrict__ n2e) {
    int i = blockIdx.x * blockDim.x + threadIdx.x;
    if (i < NEDGE) {
        int n = n2e[i];
        int p = atomicAdd(&g_cursor[n], 1);
        g_ebn[g_off[n] + p] = i;
    }
}

// ================= edge kernel: tf32 MMA dual GEMM =================
// M=64 edges/block, N=192 (0..127 -> W_node_edge, 128..191 -> W_edge_self), K=320
// 8 warps: rowBase=(w>>1)*16, colBase=(w&1)*96 (12 n8-tiles each)
#define E_PAD 324   // mod 32 == 4 -> conflict-free A frags
#define E_WPAD 200  // mod 32 == 8 -> conflict-free B frags
__global__ void __launch_bounds__(256, 2) k_edge(
    const float* __restrict__ node_ext, const float* __restrict__ edge_ebd,
    const float* __restrict__ sw,
    const int* __restrict__ n2e, const int* __restrict__ nx2e,
    const float* __restrict__ Wne, const float* __restrict__ bne,
    const float* __restrict__ Wes, const float* __restrict__ bes,
    const float* __restrict__ eres0, float* __restrict__ e_out)
{
    extern __shared__ float sm[];
    unsigned* infou = (unsigned*)sm;                  // [64][E_PAD] tf32 bits
    unsigned* wtu   = (unsigned*)(sm + 64 * E_PAD);   // [16][E_WPAD] tf32 bits
    const int tid = threadIdx.x;
    const int lane = tid & 31, warp = tid >> 5;
    const int e0 = blockIdx.x * 64;

    // gather edge_info = [node_i(128) | nei_node(128) | edge_ebd(64)], tf32-rounded
    #pragma unroll
    for (int i = 0; i < 8; i++) {
        int el = warp * 8 + i;
        int e = e0 + el;
        int ni = n2e[e], nx = nx2e[e];
        const float4* pn = (const float4*)(node_ext + (size_t)ni * NDIM);
        const float4* px = (const float4*)(node_ext + (size_t)nx * NDIM);
        const float4* pe = (const float4*)(edge_ebd + (size_t)e  * EDIM);
        for (int c = lane; c < 80; c += 32) {
            float4 v;
            if (c < 32)      v = pn[c];
            else if (c < 64) v = px[c - 32];
            else             v = pe[c - 64];
            uint4 u;
            u.x = tf32_bits(v.x); u.y = tf32_bits(v.y);
            u.z = tf32_bits(v.z); u.w = tf32_bits(v.w);
            *(uint4*)(infou + el * E_PAD + c * 4) = u;
        }
    }

    const int gid = lane >> 2, tig = lane & 3;
    const int rowBase = (warp >> 1) * 16;
    const int colBase = (warp & 1) * 96;
    float acc[12][4];
    #pragma unroll
    for (int i = 0; i < 12; i++)
        #pragma unroll
        for (int j = 0; j < 4; j++) acc[i][j] = 0.f;

    const unsigned* arow0 = infou + (rowBase + gid) * E_PAD;
    const unsigned* arow1 = arow0 + 8 * E_PAD;

    for (int k0 = 0; k0 < 320; k0 += 16) {
        __syncthreads();
        #pragma unroll
        for (int i = 0; i < 12; i++) {
            int idx = i * 256 + tid;
            int kk = idx / 192, c = idx - kk * 192;
            float v = (c < 128) ? Wne[(size_t)(k0 + kk) * 128 + c]
                                : Wes[(size_t)(k0 + kk) * 64 + (c - 128)];
            wtu[kk * E_WPAD + c] = tf32_bits(v);
        }
        __syncthreads();
        #pragma unroll
        for (int ks = 0; ks < 16; ks += 8) {
            int kb = k0 + ks;
            unsigned a0 = arow0[kb + tig];
            unsigned a2 = arow0[kb + tig + 4];
            unsigned a1 = arow1[kb + tig];
            unsigned a3 = arow1[kb + tig + 4];
            const unsigned* b0p = wtu + (ks + tig) * E_WPAD + colBase + gid;
            const unsigned* b1p = b0p + 4 * E_WPAD;
            #pragma unroll
            for (int nt = 0; nt < 12; nt++) {
                mma_tf32(acc[nt], a0, a1, a2, a3, b0p[nt * 8], b1p[nt * 8]);
            }
        }
    }

    // epilogue: rows eg0 = e0+rowBase+gid, eg1 = eg0+8; cols c = colBase+nt*8+2*tig
    const int eg0 = e0 + rowBase + gid;
    const int eg1 = eg0 + 8;
    const float sw0 = sw[eg0], sw1 = sw[eg1];
    #pragma unroll
    for (int nt = 0; nt < 12; nt++) {
        int c = colBase + nt * 8 + 2 * tig;
        if (c < 128) {
            float bb0 = bne[c], bb1 = bne[c + 1];
            float2 o0, o1;
            o0.x = silu_f(acc[nt][0] + bb0) * sw0;
            o0.y = silu_f(acc[nt][1] + bb1) * sw0;
            o1.x = silu_f(acc[nt][2] + bb0) * sw1;
            o1.y = silu_f(acc[nt][3] + bb1) * sw1;
            *(float2*)&g_edge_upd[(size_t)eg0 * 128 + c] = o0;
            *(float2*)&g_edge_upd[(size_t)eg1 * 128 + c] = o1;
        } else {
            int cc = c - 128;
            float bb0 = bes[cc], bb1 = bes[cc + 1];
            float rr0 = eres0[cc], rr1 = eres0[cc + 1];
            float2 base0 = *(const float2*)&edge_ebd[(size_t)eg0 * 64 + cc];
            float2 base1 = *(const float2*)&edge_ebd[(size_t)eg1 * 64 + cc];
            float2 o0, o1;
            o0.x = base0.x + rr0 * silu_f(acc[nt][0] + bb0);
            o0.y = base0.y + rr1 * silu_f(acc[nt][1] + bb1);
            o1.x = base1.x + rr0 * silu_f(acc[nt][2] + bb0);
            o1.y = base1.y + rr1 * silu_f(acc[nt][3] + bb1);
            *(float2*)&e_out[(size_t)eg0 * 64 + cc] = o0;
            *(float2*)&e_out[(size_t)eg1 * 64 + cc] = o1;
        }
    }
}

// ================= angle kernel: tf32 MMA dual GEMM =================
// M=64 angles/block, N=96 (0..63 -> W_edge_angle1, 64..95 -> W_angle_self), K=288
// 8 warps: rowBase=(w>>1)*16, colBase=(w&1)*48 (6 n8-tiles each)
#define A_PAD 292   // mod 32 == 4
#define A_WPAD 104  // mod 32 == 8
__global__ void __launch_bounds__(256, 2) k_angle(
    const float* __restrict__ angle_ebd, const float* __restrict__ node_ext,
    const float* __restrict__ edge_ebd, const float* __restrict__ a_sw,
    const int* __restrict__ n2a, const int* __restrict__ eij2a, const int* __restrict__ eik2a,
    const float* __restrict__ W1, const float* __restrict__ b1,
    const float* __restrict__ Wa, const float* __restrict__ ba,
    const float* __restrict__ ares0, float* __restrict__ a_out)
{
    extern __shared__ float sm[];
    unsigned* infou = (unsigned*)sm;                  // [64][A_PAD]
    unsigned* wtu   = (unsigned*)(sm + 64 * A_PAD);   // [16][A_WPAD]
    const int tid = threadIdx.x;
    const int lane = tid & 31, warp = tid >> 5;
    const int a0g = blockIdx.x * 64;

    // gather angle_info = [angle(32) | node(128) | edge_ik(64) | edge_ij(64)]
    #pragma unroll
    for (int i = 0; i < 8; i++) {
        int al = warp * 8 + i;
        int ang = a0g + al;
        const float4* pa  = (const float4*)(angle_ebd + (size_t)ang * ADIM);
        const float4* pn  = (const float4*)(node_ext + (size_t)n2a[ang] * NDIM);
        const float4* pik = (const float4*)(edge_ebd + (size_t)eik2a[ang] * EDIM);
        const float4* pij = (const float4*)(edge_ebd + (size_t)eij2a[ang] * EDIM);
        for (int c = lane; c < 72; c += 32) {
            float4 v;
            if (c < 8)       v = pa[c];
            else if (c < 40) v = pn[c - 8];
            else if (c < 56) v = pik[c - 40];
            else             v = pij[c - 56];
            uint4 u;
            u.x = tf32_bits(v.x); u.y = tf32_bits(v.y);
            u.z = tf32_bits(v.z); u.w = tf32_bits(v.w);
            *(uint4*)(infou + al * A_PAD + c * 4) = u;
        }
    }

    const int gid = lane >> 2, tig = lane & 3;
    const int rowBase = (warp >> 1) * 16;
    const int colBase = (warp & 1) * 48;
    float acc[6][4];
    #pragma unroll
    for (int i = 0; i < 6; i++)
        #pragma unroll
        for (int j = 0; j < 4; j++) acc[i][j] = 0.f;

    const unsigned* arow0 = infou + (rowBase + gid) * A_PAD;
    const unsigned* arow1 = arow0 + 8 * A_PAD;

    for (int k0 = 0; k0 < 288; k0 += 16) {
        __syncthreads();
        #pragma unroll
        for (int i = 0; i < 6; i++) {
            int idx = i * 256 + tid;
            int kk = idx / 96, c = idx - kk * 96;
            float v = (c < 64) ? W1[(size_t)(k0 + kk) * 64 + c]
                               : Wa[(size_t)(k0 + kk) * 32 + (c - 64)];
            wtu[kk * A_WPAD + c] = tf32_bits(v);
        }
        __syncthreads();
        #pragma unroll
        for (int ks = 0; ks < 16; ks += 8) {
            int kb = k0 + ks;
            unsigned a0 = arow0[kb + tig];
            unsigned a2 = arow0[kb + tig + 4];
            unsigned a1 = arow1[kb + tig];
            unsigned a3 = arow1[kb + tig + 4];
            const unsigned* b0p = wtu + (ks + tig) * A_WPAD + colBase + gid;
            const unsigned* b1p = b0p + 4 * A_WPAD;
            #pragma unroll
            for (int nt = 0; nt < 6; nt++) {
                mma_tf32(acc[nt], a0, a1, a2, a3, b0p[nt * 8], b1p[nt * 8]);
            }
        }
    }

    // epilogue
    const int ag0 = a0g + rowBase + gid;
    const int ag1 = ag0 + 8;
    const float s0 = a_sw[ag0], s1 = a_sw[ag1];
    const int e0i = eij2a[ag0], e1i = eij2a[ag1];
    #pragma unroll
    for (int nt = 0; nt < 6; nt++) {
        int c = colBase + nt * 8 + 2 * tig;
        if (c < 64) {
            float bb0 = b1[c], bb1 = b1[c + 1];
            atomicAdd(&g_reduced[(size_t)e0i * 64 + c],     silu_f(acc[nt][0] + bb0) * s0);
            atomicAdd(&g_reduced[(size_t)e0i * 64 + c + 1], silu_f(acc[nt][1] + bb1) * s0);
            atomicAdd(&g_reduced[(size_t)e1i * 64 + c],     silu_f(acc[nt][2] + bb0) * s1);
            atomicAdd(&g_reduced[(size_t)e1i * 64 + c + 1], silu_f(acc[nt][3] + bb1) * s1);
        } else {
            int cc = c - 64;
            float bb0 = ba[cc], bb1 = ba[cc + 1];
            float rr0 = ares0[cc], rr1 = ares0[cc + 1];
            float2 base0 = *(const float2*)&angle_ebd[(size_t)ag0 * 32 + cc];
            float2 base1 = *(const float2*)&angle_ebd[(size_t)ag1 * 32 + cc];
            float2 o0, o1;
            o0.x = base0.x + rr0 * silu_f(acc[nt][0] + bb0);
            o0.y = base0.y + rr1 * silu_f(acc[nt][1] + bb1);
            o1.x = base1.x + rr0 * silu_f(acc[nt][2] + bb0);
            o1.y = base1.y + rr1 * silu_f(acc[nt][3] + bb1);
            *(float2*)&a_out[(size_t)ag0 * 32 + cc] = o0;
            *(float2*)&a_out[(size_t)ag1 * 32 + cc] = o1;
        }
    }
}

// ================= node kernel: 4 nodes/block, CSR reductions + sym + GEMMs =================
__global__ void __launch_bounds__(128) k_node(
    const float* __restrict__ node_ext, const float* __restrict__ edge_ebd,
    const float* __restrict__ sw, const float* __restrict__ h2,
    const int* __restrict__ nx2e,
    const float* __restrict__ Wns, const float* __restrict__ bns,
    const float* __restrict__ Wsym, const float* __restrict__ bsym,
    const float* __restrict__ nr0, const float* __restrict__ nr1, const float* __restrict__ nr2,
    float* __restrict__ n_out)
{
    __shared__ float s_hn[3][128];
    __shared__ float s_he[3][64];
    __shared__ float s_sym[4][768];
    __shared__ float s_node[4][128];

    const int nb = blockIdx.x * 4;
    const int t = threadIdx.x;
    float msgv[4], nodev[4];
    const float sc = rsqrtf(6.4f);

    for (int nn = 0; nn < 4; nn++) {
        const int n = nb + nn;
        const int beg = g_off[n], end = g_off[n + 1];

        float hn0 = 0.f, hn1 = 0.f, hn2 = 0.f;
        float he0 = 0.f, he1 = 0.f, he2 = 0.f;
        float msg = 0.f;
        nodev[nn] = node_ext[(size_t)n * 128 + t];
        s_node[nn][t] = nodev[nn];

        int e_cur = (beg < end) ? g_ebn[beg] : 0;
        int nx_cur = (beg < end) ? nx2e[e_cur] : 0;
        for (int idx = beg; idx < end; idx++) {
            int e = e_cur, nx = nx_cur;
            if (idx + 1 < end) {
                e_cur = g_ebn[idx + 1];
                nx_cur = nx2e[e_cur];
            }
            float swv = sw[e];
            float hx = h2[e * 3 + 0] * swv;
            float hy = h2[e * 3 + 1] * swv;
            float hz = h2[e * 3 + 2] * swv;
            float nv = node_ext[(size_t)nx * 128 + t];
            float mv = g_edge_upd[(size_t)e * 128 + t];
            hn0 += hx * nv; hn1 += hy * nv; hn2 += hz * nv;
            msg += mv;
            if (t < 64) {
                float ev = edge_ebd[(size_t)e * 64 + t];
                he0 += hx * ev; he1 += hy * ev; he2 += hz * ev;
            }
        }
        msgv[nn] = msg;

        __syncthreads();   // s_hn/s_he reuse across nn
        s_hn[0][t] = hn0 * sc; s_hn[1][t] = hn1 * sc; s_hn[2][t] = hn2 * sc;
        if (t < 64) { s_he[0][t] = he0 * sc; s_he[1][t] = he1 * sc; s_he[2][t] = he2 * sc; }
        __syncthreads();

        #pragma unroll
        for (int a = 0; a < 4; a++) {
            if (t < 64)
                s_sym[nn][a * 64 + t] = (s_he[0][a] * s_he[0][t] + s_he[1][a] * s_he[1][t] +
                                         s_he[2][a] * s_he[2][t]) * (1.f / 3.f);
            s_sym[nn][256 + a * 128 + t] = (s_hn[0][a] * s_hn[0][t] + s_hn[1][a] * s_hn[1][t] +
                                            s_hn[2][a] * s_hn[2][t]) * (1.f / 3.f);
        }
    }
    __syncthreads();

    float accS[4] = {0.f, 0.f, 0.f, 0.f};
    float accY[4] = {0.f, 0.f, 0.f, 0.f};

    #pragma unroll 4
    for (int k = 0; k < 128; k++) {
        float w = Wns[(size_t)k * 128 + t];
        #pragma unroll
        for (int nn = 0; nn < 4; nn++) accS[nn] += s_node[nn][k] * w;
    }
    #pragma unroll 4
    for (int k = 0; k < 768; k++) {
        float w = Wsym[(size_t)k * 128 + t];
        #pragma unroll
        for (int nn = 0; nn < 4; nn++) accY[nn] += s_sym[nn][k] * w;
    }

    const float bS = bns[t], bY = bsym[t];
    const float r0 = nr0[t], r1 = nr1[t], r2 = nr2[t];
    #pragma unroll
    for (int nn = 0; nn < 4; nn++) {
        float out = nodev[nn] + r0 * silu_f(accS[nn] + bS) + r1 * silu_f(accY[nn] + bY)
                  + r2 * (msgv[nn] * (1.f / 6.4f));
        n_out[(size_t)(nb + nn) * 128 + t] = out;
    }
}

// ================= edge2 kernel: reduced(64) @ W_edge_angle2(64x64) =================
__global__ void __launch_bounds__(256) k_edge2(
    const float* __restrict__ W2, const float* __restrict__ b2,
    const float* __restrict__ eres1, float* __restrict__ e_out)
{
    __shared__ float w2s[64 * 64];
    __shared__ float in2[64 * 65];
    __shared__ float b2s[64];
    const int tid = threadIdx.x;
    const int e0 = blockIdx.x * 64;

    #pragma unroll
    for (int i = 0; i < 16; i++) {
        int idx = i * 256 + tid;
        w2s[idx] = W2[idx];
    }
    if (tid < 64) b2s[tid] = b2[tid];
    #pragma unroll
    for (int i = 0; i < 16; i++) {
        int idx = i * 256 + tid;
        int e = idx >> 6, k = idx & 63;
        in2[e * 65 + k] = g_reduced[(size_t)(e0 + e) * 64 + k];
    }
    __syncthreads();

    const int tx = tid & 15, ty = tid >> 4;
    float acc[4][4];
    #pragma unroll
    for (int i = 0; i < 4; i++)
        #pragma unroll
        for (int j = 0; j < 4; j++) acc[i][j] = 0.f;

    #pragma unroll 4
    for (int k = 0; k < 64; k++) {
        float4 wv = *(const float4*)&w2s[k * 64 + tx * 4];
        float w[4] = { wv.x, wv.y, wv.z, wv.w };
        #pragma unroll
        for (int i = 0; i < 4; i++) {
            float a = in2[(ty * 4 + i) * 65 + k];
            #pragma unroll
            for (int j = 0; j < 4; j++) acc[i][j] += a * w[j];
        }
    }

    #pragma unroll
    for (int i = 0; i < 4; i++) {
        int e = e0 + ty * 4 + i;
        #pragma unroll
        for (int j = 0; j < 4; j++) {
            int c = tx * 4 + j;
            float y = silu_f(acc[i][j] + b2s[c]);
            e_out[(size_t)e * 64 + c] += eres1[c] * y;
        }
    }
}

// ---------------- launch ----------------
extern "C" void kernel_launch(void* const* d_in, const int* in_sizes, int n_in,
                              void* d_out, int out_size)
{
    const float* node_ext  = (const float*)d_in[0];
    const float* edge_ebd  = (const float*)d_in[1];
    const float* h2        = (const float*)d_in[2];
    const float* angle_ebd = (const float*)d_in[3];
    const float* sw        = (const float*)d_in[6];
    const float* a_sw      = (const float*)d_in[9];
    const int*   edge_index  = (const int*)d_in[10];
    const int*   angle_index = (const int*)d_in[11];
    const int* n2e   = edge_index;
    const int* nx2e  = edge_index + NEDGE;
    const int* n2a   = angle_index;
    const int* eij2a = angle_index + NANGLE;
    const int* eik2a = angle_index + 2 * NANGLE;

    const float* Wns  = (const float*)d_in[12];
    const float* bns  = (const float*)d_in[13];
    const float* Wsym = (const float*)d_in[14];
    const float* bsym = (const float*)d_in[15];
    const float* Wne  = (const float*)d_in[16];
    const float* bne  = (const float*)d_in[17];
    const float* Wes  = (const float*)d_in[18];
    const float* bes  = (const float*)d_in[19];
    const float* W1   = (const float*)d_in[20];
    const float* b1   = (const float*)d_in[21];
    const float* W2   = (const float*)d_in[22];
    const float* b2   = (const float*)d_in[23];
    const float* Wa   = (const float*)d_in[24];
    const float* ba   = (const float*)d_in[25];
    const float* nr0  = (const float*)d_in[26];
    const float* nr1  = (const float*)d_in[27];
    const float* nr2  = (const float*)d_in[28];
    const float* er0  = (const float*)d_in[29];
    const float* er1  = (const float*)d_in[30];
    const float* ar0  = (const float*)d_in[31];

    float* out   = (float*)d_out;
    float* n_out = out;
    float* e_out = out + (size_t)NLOC * NDIM;
    float* a_out = out + (size_t)NLOC * NDIM + (size_t)NEDGE * EDIM;

    const int edge_smem  = (64 * E_PAD + 16 * E_WPAD) * 4;   // 95744 B
    const int angle_smem = (64 * A_PAD + 16 * A_WPAD) * 4;   // 81408 B
    cudaFuncSetAttribute(k_edge,  cudaFuncAttributeMaxDynamicSharedMemorySize, edge_smem);
    cudaFuncSetAttribute(k_angle, cudaFuncAttributeMaxDynamicSharedMemorySize, angle_smem);

    k_zero<<<2048, 256>>>();
    k_hist<<<NEDGE / 256, 256>>>(n2e);
    k_scan<<<1, 1024>>>();
    k_scatter<<<NEDGE / 256, 256>>>(n2e);

    k_edge<<<NEDGE / 64, 256, edge_smem>>>(node_ext, edge_ebd, sw, n2e, nx2e,
                                           Wne, bne, Wes, bes, er0, e_out);
    k_node<<<NLOC / 4, 128>>>(node_ext, edge_ebd, sw, h2, nx2e,
                              Wns, bns, Wsym, bsym, nr0, nr1, nr2, n_out);
    k_angle<<<NANGLE / 64, 256, angle_smem>>>(angle_ebd, node_ext, edge_ebd, a_sw,
                                              n2a, eij2a, eik2a,
                                              W1, b1, Wa, ba, ar0, a_out);
    k_edge2<<<NEDGE / 64, 256>>>(W2, b2, er1, e_out);
}

// round 7
// speedup vs baseline: 1.6952x; 1.0367x over previous
#include <cuda_runtime.h>
#include <math.h>

// ---------------- problem constants ----------------
#define NLOC   4096
#define NALL   6144
#define NEDGE  262144
#define NANGLE 409600
#define NDIM   128
#define EDIM   64
#define ADIM   32
// dyn_e_sel = 64/10 = 6.4 ; dyn_a_sel = 10/10 = 1.0

// ---------------- scratch ----------------
__device__ float g_edge_upd[(size_t)NEDGE * NDIM];
__device__ float g_reduced [(size_t)NEDGE * EDIM];
__device__ int   g_count [NLOC];
__device__ int   g_off   [NLOC + 1];
__device__ int   g_cursor[NLOC];
__device__ int   g_ebn   [NEDGE];

__device__ __forceinline__ float silu_f(float x) {
    return x * (1.0f / (1.0f + __expf(-x)));
}

__device__ __forceinline__ unsigned tf32_bits(float f) {
    unsigned u;
    asm("cvt.rna.tf32.f32 %0, %1;" : "=r"(u) : "f"(f));
    return u;
}

__device__ __forceinline__ void mma_tf32(float* d,
    unsigned a0, unsigned a1, unsigned a2, unsigned a3,
    unsigned b0, unsigned b1)
{
    asm("mma.sync.aligned.m16n8k8.row.col.f32.tf32.tf32.f32 "
        "{%0,%1,%2,%3}, {%4,%5,%6,%7}, {%8,%9}, {%0,%1,%2,%3};"
        : "+f"(d[0]), "+f"(d[1]), "+f"(d[2]), "+f"(d[3])
        : "r"(a0), "r"(a1), "r"(a2), "r"(a3), "r"(b0), "r"(b1));
}

// ---------------- small helper kernels ----------------
__global__ void k_zero() {
    int i = blockIdx.x * blockDim.x + threadIdx.x;
    int stride = gridDim.x * blockDim.x;
    float4 z = make_float4(0.f, 0.f, 0.f, 0.f);
    float4* r = (float4*)g_reduced;
    const int n4 = NEDGE * EDIM / 4;
    for (int j = i; j < n4; j += stride) r[j] = z;
    for (int j = i; j < NLOC; j += stride) { g_count[j] = 0; g_cursor[j] = 0; }
}

__global__ void k_hist(const int* __restrict__ n2e) {
    int i = blockIdx.x * blockDim.x + threadIdx.x;
    if (i < NEDGE) atomicAdd(&g_count[n2e[i]], 1);
}

__global__ void k_scan() {
    __shared__ int ss[1024];
    int t = threadIdx.x;
    int c0 = g_count[t * 4 + 0];
    int c1 = g_count[t * 4 + 1];
    int c2 = g_count[t * 4 + 2];
    int c3 = g_count[t * 4 + 3];
    int p1 = c0, p2 = p1 + c1, p3 = p2 + c2, s = p3 + c3;
    ss[t] = s;
    __syncthreads();
    for (int d = 1; d < 1024; d <<= 1) {
        int v = (t >= d) ? ss[t - d] : 0;
        __syncthreads();
        ss[t] += v;
        __syncthreads();
    }
    int base = (t > 0) ? ss[t - 1] : 0;
    g_off[t * 4 + 0] = base;
    g_off[t * 4 + 1] = base + p1;
    g_off[t * 4 + 2] = base + p2;
    g_off[t * 4 + 3] = base + p3;
    if (t == 1023) g_off[NLOC] = ss[1023];
}

__global__ void k_scatter(const int* __restrict__ n2e) {
    int i = blockIdx.x * blockDim.x + threadIdx.x;
    if (i < NEDGE) {
        int n = n2e[i];
        int p = atomicAdd(&g_cursor[n], 1);
        g_ebn[g_off[n] + p] = i;
    }
}

// ================= edge kernel: tf32 MMA dual GEMM =================
// M=64 edges/block, N=192 (0..127 -> W_node_edge, 128..191 -> W_edge_self), K=320
#define E_PAD 324   // mod 32 == 4 -> conflict-free A frags
#define E_WPAD 200  // mod 32 == 8 -> conflict-free B frags
__global__ void __launch_bounds__(256, 2) k_edge(
    const float* __restrict__ node_ext, const float* __restrict__ edge_ebd,
    const float* __restrict__ sw,
    const int* __restrict__ n2e, const int* __restrict__ nx2e,
    const float* __restrict__ Wne, const float* __restrict__ bne,
    const float* __restrict__ Wes, const float* __restrict__ bes,
    const float* __restrict__ eres0, float* __restrict__ e_out)
{
    extern __shared__ float sm[];
    unsigned* infou = (unsigned*)sm;                  // [64][E_PAD] tf32 bits
    unsigned* wtu   = (unsigned*)(sm + 64 * E_PAD);   // [16][E_WPAD] tf32 bits
    const int tid = threadIdx.x;
    const int lane = tid & 31, warp = tid >> 5;
    const int e0 = blockIdx.x * 64;

    #pragma unroll
    for (int i = 0; i < 8; i++) {
        int el = warp * 8 + i;
        int e = e0 + el;
        int ni = n2e[e], nx = nx2e[e];
        const float4* pn = (const float4*)(node_ext + (size_t)ni * NDIM);
        const float4* px = (const float4*)(node_ext + (size_t)nx * NDIM);
        const float4* pe = (const float4*)(edge_ebd + (size_t)e  * EDIM);
        for (int c = lane; c < 80; c += 32) {
            float4 v;
            if (c < 32)      v = pn[c];
            else if (c < 64) v = px[c - 32];
            else             v = pe[c - 64];
            uint4 u;
            u.x = tf32_bits(v.x); u.y = tf32_bits(v.y);
            u.z = tf32_bits(v.z); u.w = tf32_bits(v.w);
            *(uint4*)(infou + el * E_PAD + c * 4) = u;
        }
    }

    const int gid = lane >> 2, tig = lane & 3;
    const int rowBase = (warp >> 1) * 16;
    const int colBase = (warp & 1) * 96;
    float acc[12][4];
    #pragma unroll
    for (int i = 0; i < 12; i++)
        #pragma unroll
        for (int j = 0; j < 4; j++) acc[i][j] = 0.f;

    const unsigned* arow0 = infou + (rowBase + gid) * E_PAD;
    const unsigned* arow1 = arow0 + 8 * E_PAD;

    for (int k0 = 0; k0 < 320; k0 += 16) {
        __syncthreads();
        #pragma unroll
        for (int i = 0; i < 12; i++) {
            int idx = i * 256 + tid;
            int kk = idx / 192, c = idx - kk * 192;
            float v = (c < 128) ? Wne[(size_t)(k0 + kk) * 128 + c]
                                : Wes[(size_t)(k0 + kk) * 64 + (c - 128)];
            wtu[kk * E_WPAD + c] = tf32_bits(v);
        }
        __syncthreads();
        #pragma unroll
        for (int ks = 0; ks < 16; ks += 8) {
            int kb = k0 + ks;
            unsigned a0 = arow0[kb + tig];
            unsigned a2 = arow0[kb + tig + 4];
            unsigned a1 = arow1[kb + tig];
            unsigned a3 = arow1[kb + tig + 4];
            const unsigned* b0p = wtu + (ks + tig) * E_WPAD + colBase + gid;
            const unsigned* b1p = b0p + 4 * E_WPAD;
            #pragma unroll
            for (int nt = 0; nt < 12; nt++) {
                mma_tf32(acc[nt], a0, a1, a2, a3, b0p[nt * 8], b1p[nt * 8]);
            }
        }
    }

    const int eg0 = e0 + rowBase + gid;
    const int eg1 = eg0 + 8;
    const float sw0 = sw[eg0], sw1 = sw[eg1];
    #pragma unroll
    for (int nt = 0; nt < 12; nt++) {
        int c = colBase + nt * 8 + 2 * tig;
        if (c < 128) {
            float bb0 = bne[c], bb1 = bne[c + 1];
            float2 o0, o1;
            o0.x = silu_f(acc[nt][0] + bb0) * sw0;
            o0.y = silu_f(acc[nt][1] + bb1) * sw0;
            o1.x = silu_f(acc[nt][2] + bb0) * sw1;
            o1.y = silu_f(acc[nt][3] + bb1) * sw1;
            *(float2*)&g_edge_upd[(size_t)eg0 * 128 + c] = o0;
            *(float2*)&g_edge_upd[(size_t)eg1 * 128 + c] = o1;
        } else {
            int cc = c - 128;
            float bb0 = bes[cc], bb1 = bes[cc + 1];
            float rr0 = eres0[cc], rr1 = eres0[cc + 1];
            float2 base0 = *(const float2*)&edge_ebd[(size_t)eg0 * 64 + cc];
            float2 base1 = *(const float2*)&edge_ebd[(size_t)eg1 * 64 + cc];
            float2 o0, o1;
            o0.x = base0.x + rr0 * silu_f(acc[nt][0] + bb0);
            o0.y = base0.y + rr1 * silu_f(acc[nt][1] + bb1);
            o1.x = base1.x + rr0 * silu_f(acc[nt][2] + bb0);
            o1.y = base1.y + rr1 * silu_f(acc[nt][3] + bb1);
            *(float2*)&e_out[(size_t)eg0 * 64 + cc] = o0;
            *(float2*)&e_out[(size_t)eg1 * 64 + cc] = o1;
        }
    }
}

// ================= angle kernel: tf32 MMA dual GEMM =================
#define A_PAD 292   // mod 32 == 4
#define A_WPAD 104  // mod 32 == 8
__global__ void __launch_bounds__(256, 2) k_angle(
    const float* __restrict__ angle_ebd, const float* __restrict__ node_ext,
    const float* __restrict__ edge_ebd, const float* __restrict__ a_sw,
    const int* __restrict__ n2a, const int* __restrict__ eij2a, const int* __restrict__ eik2a,
    const float* __restrict__ W1, const float* __restrict__ b1,
    const float* __restrict__ Wa, const float* __restrict__ ba,
    const float* __restrict__ ares0, float* __restrict__ a_out)
{
    extern __shared__ float sm[];
    unsigned* infou = (unsigned*)sm;                  // [64][A_PAD]
    unsigned* wtu   = (unsigned*)(sm + 64 * A_PAD);   // [16][A_WPAD]
    const int tid = threadIdx.x;
    const int lane = tid & 31, warp = tid >> 5;
    const int a0g = blockIdx.x * 64;

    #pragma unroll
    for (int i = 0; i < 8; i++) {
        int al = warp * 8 + i;
        int ang = a0g + al;
        const float4* pa  = (const float4*)(angle_ebd + (size_t)ang * ADIM);
        const float4* pn  = (const float4*)(node_ext + (size_t)n2a[ang] * NDIM);
        const float4* pik = (const float4*)(edge_ebd + (size_t)eik2a[ang] * EDIM);
        const float4* pij = (const float4*)(edge_ebd + (size_t)eij2a[ang] * EDIM);
        for (int c = lane; c < 72; c += 32) {
            float4 v;
            if (c < 8)       v = pa[c];
            else if (c < 40) v = pn[c - 8];
            else if (c < 56) v = pik[c - 40];
            else             v = pij[c - 56];
            uint4 u;
            u.x = tf32_bits(v.x); u.y = tf32_bits(v.y);
            u.z = tf32_bits(v.z); u.w = tf32_bits(v.w);
            *(uint4*)(infou + al * A_PAD + c * 4) = u;
        }
    }

    const int gid = lane >> 2, tig = lane & 3;
    const int rowBase = (warp >> 1) * 16;
    const int colBase = (warp & 1) * 48;
    float acc[6][4];
    #pragma unroll
    for (int i = 0; i < 6; i++)
        #pragma unroll
        for (int j = 0; j < 4; j++) acc[i][j] = 0.f;

    const unsigned* arow0 = infou + (rowBase + gid) * A_PAD;
    const unsigned* arow1 = arow0 + 8 * A_PAD;

    for (int k0 = 0; k0 < 288; k0 += 16) {
        __syncthreads();
        #pragma unroll
        for (int i = 0; i < 6; i++) {
            int idx = i * 256 + tid;
            int kk = idx / 96, c = idx - kk * 96;
            float v = (c < 64) ? W1[(size_t)(k0 + kk) * 64 + c]
                               : Wa[(size_t)(k0 + kk) * 32 + (c - 64)];
            wtu[kk * A_WPAD + c] = tf32_bits(v);
        }
        __syncthreads();
        #pragma unroll
        for (int ks = 0; ks < 16; ks += 8) {
            int kb = k0 + ks;
            unsigned a0 = arow0[kb + tig];
            unsigned a2 = arow0[kb + tig + 4];
            unsigned a1 = arow1[kb + tig];
            unsigned a3 = arow1[kb + tig + 4];
            const unsigned* b0p = wtu + (ks + tig) * A_WPAD + colBase + gid;
            const unsigned* b1p = b0p + 4 * A_WPAD;
            #pragma unroll
            for (int nt = 0; nt < 6; nt++) {
                mma_tf32(acc[nt], a0, a1, a2, a3, b0p[nt * 8], b1p[nt * 8]);
            }
        }
    }

    const int ag0 = a0g + rowBase + gid;
    const int ag1 = ag0 + 8;
    const float s0 = a_sw[ag0], s1 = a_sw[ag1];
    const int e0i = eij2a[ag0], e1i = eij2a[ag1];
    #pragma unroll
    for (int nt = 0; nt < 6; nt++) {
        int c = colBase + nt * 8 + 2 * tig;
        if (c < 64) {
            float bb0 = b1[c], bb1 = b1[c + 1];
            atomicAdd(&g_reduced[(size_t)e0i * 64 + c],     silu_f(acc[nt][0] + bb0) * s0);
            atomicAdd(&g_reduced[(size_t)e0i * 64 + c + 1], silu_f(acc[nt][1] + bb1) * s0);
            atomicAdd(&g_reduced[(size_t)e1i * 64 + c],     silu_f(acc[nt][2] + bb0) * s1);
            atomicAdd(&g_reduced[(size_t)e1i * 64 + c + 1], silu_f(acc[nt][3] + bb1) * s1);
        } else {
            int cc = c - 64;
            float bb0 = ba[cc], bb1 = ba[cc + 1];
            float rr0 = ares0[cc], rr1 = ares0[cc + 1];
            float2 base0 = *(const float2*)&angle_ebd[(size_t)ag0 * 32 + cc];
            float2 base1 = *(const float2*)&angle_ebd[(size_t)ag1 * 32 + cc];
            float2 o0, o1;
            o0.x = base0.x + rr0 * silu_f(acc[nt][0] + bb0);
            o0.y = base0.y + rr1 * silu_f(acc[nt][1] + bb1);
            o1.x = base1.x + rr0 * silu_f(acc[nt][2] + bb0);
            o1.y = base1.y + rr1 * silu_f(acc[nt][3] + bb1);
            *(float2*)&a_out[(size_t)ag0 * 32 + cc] = o0;
            *(float2*)&a_out[(size_t)ag1 * 32 + cc] = o1;
        }
    }
}

// ================= node kernel v2: 4 nodes/block in PARALLEL (512 threads) =================
// Gather phase: thread group g=t>>7 handles node nb+g (4x MLP vs serial).
// GEMM phase: split-K over 4 quarters, each thread computes partials for all 4 nodes
// (weight element loaded once per block), then smem reduction.
__global__ void __launch_bounds__(512) k_node(
    const float* __restrict__ node_ext, const float* __restrict__ edge_ebd,
    const float* __restrict__ sw, const float* __restrict__ h2,
    const int* __restrict__ nx2e,
    const float* __restrict__ Wns, const float* __restrict__ bns,
    const float* __restrict__ Wsym, const float* __restrict__ bsym,
    const float* __restrict__ nr0, const float* __restrict__ nr1, const float* __restrict__ nr2,
    float* __restrict__ n_out)
{
    __shared__ float s_hn[4][3][128];
    __shared__ float s_he[4][3][64];
    __shared__ float s_sym[4][768];
    __shared__ float s_node[4][128];
    __shared__ float s_msg[4][128];
    __shared__ float s_pS[4][4][128];   // [quarter][node][col]
    __shared__ float s_pY[4][4][128];

    const int nb = blockIdx.x * 4;
    const int t = threadIdx.x;
    const int g = t >> 7;        // node group 0..3
    const int tl = t & 127;      // dim/col 0..127
    const float sc = rsqrtf(6.4f);

    // ---- gather phase: each group walks its own node's CSR list ----
    {
        const int n = nb + g;
        const int beg = g_off[n], end = g_off[n + 1];

        float hn0 = 0.f, hn1 = 0.f, hn2 = 0.f;
        float he0 = 0.f, he1 = 0.f, he2 = 0.f;
        float msg = 0.f;
        float nodev = node_ext[(size_t)n * 128 + tl];
        s_node[g][tl] = nodev;

        int e_cur = (beg < end) ? g_ebn[beg] : 0;
        int nx_cur = (beg < end) ? nx2e[e_cur] : 0;
        for (int idx = beg; idx < end; idx++) {
            int e = e_cur, nx = nx_cur;
            if (idx + 1 < end) {
                e_cur = g_ebn[idx + 1];
                nx_cur = nx2e[e_cur];
            }
            float swv = sw[e];
            float hx = h2[e * 3 + 0] * swv;
            float hy = h2[e * 3 + 1] * swv;
            float hz = h2[e * 3 + 2] * swv;
            float nv = node_ext[(size_t)nx * 128 + tl];
            float mv = g_edge_upd[(size_t)e * 128 + tl];
            hn0 += hx * nv; hn1 += hy * nv; hn2 += hz * nv;
            msg += mv;
            if (tl < 64) {
                float ev = edge_ebd[(size_t)e * 64 + tl];
                he0 += hx * ev; he1 += hy * ev; he2 += hz * ev;
            }
        }

        s_hn[g][0][tl] = hn0 * sc; s_hn[g][1][tl] = hn1 * sc; s_hn[g][2][tl] = hn2 * sc;
        if (tl < 64) { s_he[g][0][tl] = he0 * sc; s_he[g][1][tl] = he1 * sc; s_he[g][2][tl] = he2 * sc; }
        s_msg[g][tl] = msg;
    }
    __syncthreads();

    // ---- sym: group g builds node g's 768-dim sym vector ----
    #pragma unroll
    for (int a = 0; a < 4; a++) {
        if (tl < 64)
            s_sym[g][a * 64 + tl] = (s_he[g][0][a] * s_he[g][0][tl] + s_he[g][1][a] * s_he[g][1][tl] +
                                     s_he[g][2][a] * s_he[g][2][tl]) * (1.f / 3.f);
        s_sym[g][256 + a * 128 + tl] = (s_hn[g][0][a] * s_hn[g][0][tl] + s_hn[g][1][a] * s_hn[g][1][tl] +
                                        s_hn[g][2][a] * s_hn[g][2][tl]) * (1.f / 3.f);
    }
    __syncthreads();

    // ---- split-K GEMMs: quarter q = g, col c = tl; partials for all 4 nodes ----
    {
        const int q = g, c = tl;
        float pS[4] = {0.f, 0.f, 0.f, 0.f};
        float pY[4] = {0.f, 0.f, 0.f, 0.f};

        #pragma unroll 4
        for (int k = q * 32; k < q * 32 + 32; k++) {
            float w = Wns[(size_t)k * 128 + c];
            #pragma unroll
            for (int nn = 0; nn < 4; nn++) pS[nn] += s_node[nn][k] * w;
        }
        #pragma unroll 4
        for (int k = q * 192; k < q * 192 + 192; k++) {
            float w = Wsym[(size_t)k * 128 + c];
            #pragma unroll
            for (int nn = 0; nn < 4; nn++) pY[nn] += s_sym[nn][k] * w;
        }
        #pragma unroll
        for (int nn = 0; nn < 4; nn++) {
            s_pS[q][nn][c] = pS[nn];
            s_pY[q][nn][c] = pY[nn];
        }
    }
    __syncthreads();

    // ---- reduce + epilogue: node nn = g, col c = tl ----
    {
        const int nn = g, c = tl;
        float accS = s_pS[0][nn][c] + s_pS[1][nn][c] + s_pS[2][nn][c] + s_pS[3][nn][c];
        float accY = s_pY[0][nn][c] + s_pY[1][nn][c] + s_pY[2][nn][c] + s_pY[3][nn][c];
        float out = s_node[nn][c]
                  + nr0[c] * silu_f(accS + bns[c])
                  + nr1[c] * silu_f(accY + bsym[c])
                  + nr2[c] * (s_msg[nn][c] * (1.f / 6.4f));
        n_out[(size_t)(nb + nn) * 128 + c] = out;
    }
}

// ================= edge2 kernel: reduced(64) @ W_edge_angle2(64x64) =================
__global__ void __launch_bounds__(256) k_edge2(
    const float* __restrict__ W2, const float* __restrict__ b2,
    const float* __restrict__ eres1, float* __restrict__ e_out)
{
    __shared__ float w2s[64 * 64];
    __shared__ float in2[64 * 65];
    __shared__ float b2s[64];
    const int tid = threadIdx.x;
    const int e0 = blockIdx.x * 64;

    #pragma unroll
    for (int i = 0; i < 16; i++) {
        int idx = i * 256 + tid;
        w2s[idx] = W2[idx];
    }
    if (tid < 64) b2s[tid] = b2[tid];
    #pragma unroll
    for (int i = 0; i < 16; i++) {
        int idx = i * 256 + tid;
        int e = idx >> 6, k = idx & 63;
        in2[e * 65 + k] = g_reduced[(size_t)(e0 + e) * 64 + k];
    }
    __syncthreads();

    const int tx = tid & 15, ty = tid >> 4;
    float acc[4][4];
    #pragma unroll
    for (int i = 0; i < 4; i++)
        #pragma unroll
        for (int j = 0; j < 4; j++) acc[i][j] = 0.f;

    #pragma unroll 4
    for (int k = 0; k < 64; k++) {
        float4 wv = *(const float4*)&w2s[k * 64 + tx * 4];
        float w[4] = { wv.x, wv.y, wv.z, wv.w };
        #pragma unroll
        for (int i = 0; i < 4; i++) {
            float a = in2[(ty * 4 + i) * 65 + k];
            #pragma unroll
            for (int j = 0; j < 4; j++) acc[i][j] += a * w[j];
        }
    }

    #pragma unroll
    for (int i = 0; i < 4; i++) {
        int e = e0 + ty * 4 + i;
        #pragma unroll
        for (int j = 0; j < 4; j++) {
            int c = tx * 4 + j;
            float y = silu_f(acc[i][j] + b2s[c]);
            e_out[(size_t)e * 64 + c] += eres1[c] * y;
        }
    }
}

// ---------------- launch ----------------
extern "C" void kernel_launch(void* const* d_in, const int* in_sizes, int n_in,
                              void* d_out, int out_size)
{
    const float* node_ext  = (const float*)d_in[0];
    const float* edge_ebd  = (const float*)d_in[1];
    const float* h2        = (const float*)d_in[2];
    const float* angle_ebd = (const float*)d_in[3];
    const float* sw        = (const float*)d_in[6];
    const float* a_sw      = (const float*)d_in[9];
    const int*   edge_index  = (const int*)d_in[10];
    const int*   angle_index = (const int*)d_in[11];
    const int* n2e   = edge_index;
    const int* nx2e  = edge_index + NEDGE;
    const int* n2a   = angle_index;
    const int* eij2a = angle_index + NANGLE;
    const int* eik2a = angle_index + 2 * NANGLE;

    const float* Wns  = (const float*)d_in[12];
    const float* bns  = (const float*)d_in[13];
    const float* Wsym = (const float*)d_in[14];
    const float* bsym = (const float*)d_in[15];
    const float* Wne  = (const float*)d_in[16];
    const float* bne  = (const float*)d_in[17];
    const float* Wes  = (const float*)d_in[18];
    const float* bes  = (const float*)d_in[19];
    const float* W1   = (const float*)d_in[20];
    const float* b1   = (const float*)d_in[21];
    const float* W2   = (const float*)d_in[22];
    const float* b2   = (const float*)d_in[23];
    const float* Wa   = (const float*)d_in[24];
    const float* ba   = (const float*)d_in[25];
    const float* nr0  = (const float*)d_in[26];
    const float* nr1  = (const float*)d_in[27];
    const float* nr2  = (const float*)d_in[28];
    const float* er0  = (const float*)d_in[29];
    const float* er1  = (const float*)d_in[30];
    const float* ar0  = (const float*)d_in[31];

    float* out   = (float*)d_out;
    float* n_out = out;
    float* e_out = out + (size_t)NLOC * NDIM;
    float* a_out = out + (size_t)NLOC * NDIM + (size_t)NEDGE * EDIM;

    const int edge_smem  = (64 * E_PAD + 16 * E_WPAD) * 4;   // 95744 B
    const int angle_smem = (64 * A_PAD + 16 * A_WPAD) * 4;   // 81408 B
    cudaFuncSetAttribute(k_edge,  cudaFuncAttributeMaxDynamicSharedMemorySize, edge_smem);
    cudaFuncSetAttribute(k_angle, cudaFuncAttributeMaxDynamicSharedMemorySize, angle_smem);

    // Launch order: k_edge at index 3 so ncu's capture (observed to land on the
    // 4th app launch) profiles the tensor kernel instead of k_scatter.
    k_zero<<<2048, 256>>>();
    k_hist<<<NEDGE / 256, 256>>>(n2e);
    k_scan<<<1, 1024>>>();
    k_edge<<<NEDGE / 64, 256, edge_smem>>>(node_ext, edge_ebd, sw, n2e, nx2e,
                                           Wne, bne, Wes, bes, er0, e_out);
    k_scatter<<<NEDGE / 256, 256>>>(n2e);
    k_node<<<NLOC / 4, 512>>>(node_ext, edge_ebd, sw, h2, nx2e,
                              Wns, bns, Wsym, bsym, nr0, nr1, nr2, n_out);
    k_angle<<<NANGLE / 64, 256, angle_smem>>>(angle_ebd, node_ext, edge_ebd, a_sw,
                                              n2a, eij2a, eik2a,
                                              W1, b1, Wa, ba, ar0, a_out);
    k_edge2<<<NEDGE / 64, 256>>>(W2, b2, er1, e_out);
}

// round 10
// speedup vs baseline: 2.4883x; 1.4678x over previous
#include <cuda_runtime.h>
#include <cuda_bf16.h>
#include <math.h>

// ---------------- problem constants ----------------
#define NLOC   4096
#define NALL   6144
#define NEDGE  262144
#define NANGLE 409600
#define NDIM   128
#define EDIM   64
#define ADIM   32
// dyn_e_sel = 64/10 = 6.4 ; dyn_a_sel = 10/10 = 1.0

// ---------------- scratch ----------------
__device__ float g_edge_upd[(size_t)NEDGE * NDIM];
__device__ float g_reduced [(size_t)NEDGE * EDIM];
__device__ int   g_count [NLOC];
__device__ int   g_off   [NLOC + 1];
__device__ int   g_cursor[NLOC];
__device__ int   g_ebn   [NEDGE];

__device__ __forceinline__ float silu_f(float x) {
    return x * (1.0f / (1.0f + __expf(-x)));
}

// pack two floats into bf16x2 (lo = first arg in low 16 bits)
__device__ __forceinline__ unsigned bf16x2(float lo, float hi) {
    __nv_bfloat162 h = __float22bfloat162_rn(make_float2(lo, hi));
    return *reinterpret_cast<unsigned*>(&h);
}

__device__ __forceinline__ void mma_bf16(float* d,
    unsigned a0, unsigned a1, unsigned a2, unsigned a3,
    unsigned b0, unsigned b1)
{
    asm("mma.sync.aligned.m16n8k16.row.col.f32.bf16.bf16.f32 "
        "{%0,%1,%2,%3}, {%4,%5,%6,%7}, {%8,%9}, {%0,%1,%2,%3};"
        : "+f"(d[0]), "+f"(d[1]), "+f"(d[2]), "+f"(d[3])
        : "r"(a0), "r"(a1), "r"(a2), "r"(a3), "r"(b0), "r"(b1));
}

// ---------------- small helper kernels ----------------
__global__ void k_zero() {
    int i = blockIdx.x * blockDim.x + threadIdx.x;
    int stride = gridDim.x * blockDim.x;
    float4 z = make_float4(0.f, 0.f, 0.f, 0.f);
    float4* r = (float4*)g_reduced;
    const int n4 = NEDGE * EDIM / 4;
    for (int j = i; j < n4; j += stride) r[j] = z;
    for (int j = i; j < NLOC; j += stride) { g_count[j] = 0; g_cursor[j] = 0; }
}

__global__ void k_hist(const int* __restrict__ n2e) {
    int i = blockIdx.x * blockDim.x + threadIdx.x;
    if (i < NEDGE) atomicAdd(&g_count[n2e[i]], 1);
}

__global__ void k_scan() {
    __shared__ int ss[1024];
    int t = threadIdx.x;
    int c0 = g_count[t * 4 + 0];
    int c1 = g_count[t * 4 + 1];
    int c2 = g_count[t * 4 + 2];
    int c3 = g_count[t * 4 + 3];
    int p1 = c0, p2 = p1 + c1, p3 = p2 + c2, s = p3 + c3;
    ss[t] = s;
    __syncthreads();
    for (int d = 1; d < 1024; d <<= 1) {
        int v = (t >= d) ? ss[t - d] : 0;
        __syncthreads();
        ss[t] += v;
        __syncthreads();
    }
    int base = (t > 0) ? ss[t - 1] : 0;
    g_off[t * 4 + 0] = base;
    g_off[t * 4 + 1] = base + p1;
    g_off[t * 4 + 2] = base + p2;
    g_off[t * 4 + 3] = base + p3;
    if (t == 1023) g_off[NLOC] = ss[1023];
}

__global__ void k_scatter(const int* __restrict__ n2e) {
    int i = blockIdx.x * blockDim.x + threadIdx.x;
    if (i < NEDGE) {
        int n = n2e[i];
        int p = atomicAdd(&g_cursor[n], 1);
        g_ebn[g_off[n] + p] = i;
    }
}

// ================= edge kernel: bf16 MMA dual GEMM =================
// M=64 edges/block, N=192 (cols 0..127 -> W_node_edge, 128..191 -> W_edge_self), K=320.
// 8 warps: rowBase=(warp&1)*32, colBase=(warp>>1)*48 -> each warp 2 m16-tiles x 6 n8-tiles.
#define E2_PAD 164   // words/row; 164 % 32 == 4 -> A frag LDS conflict-free
#define E2_WPAD 200  // words/kpair; 200 % 32 == 8 -> B frag LDS conflict-free
__global__ void __launch_bounds__(256, 3) k_edge(
    const float* __restrict__ node_ext, const float* __restrict__ edge_ebd,
    const float* __restrict__ sw,
    const int* __restrict__ n2e, const int* __restrict__ nx2e,
    const float* __restrict__ Wne, const float* __restrict__ bne,
    const float* __restrict__ Wes, const float* __restrict__ bes,
    const float* __restrict__ eres0, float* __restrict__ e_out)
{
    extern __shared__ unsigned smu[];
    unsigned* infou = smu;                       // [64][E2_PAD] bf16x2 words
    unsigned* wtu   = smu + 64 * E2_PAD;         // [16][E2_WPAD] bf16x2 words
    const int tid = threadIdx.x;
    const int lane = tid & 31;
    const int warp = tid >> 5;
    const int e0 = blockIdx.x * 64;

    // gather edge_info = [node_i(128) | nei_node(128) | edge_ebd(64)] -> bf16x2
    #pragma unroll
    for (int i = 0; i < 8; i++) {
        int el = warp * 8 + i;
        int e = e0 + el;
        int ni = n2e[e], nx = nx2e[e];
        const float4* pn = (const float4*)(node_ext + (size_t)ni * NDIM);
        const float4* px = (const float4*)(node_ext + (size_t)nx * NDIM);
        const float4* pe = (const float4*)(edge_ebd + (size_t)e  * EDIM);
        for (int c = lane; c < 80; c += 32) {
            float4 v;
            if (c < 32)      v = pn[c];
            else if (c < 64) v = px[c - 32];
            else             v = pe[c - 64];
            uint2 u;
            u.x = bf16x2(v.x, v.y);
            u.y = bf16x2(v.z, v.w);
            *(uint2*)(infou + el * E2_PAD + c * 2) = u;
        }
    }

    const int gid = lane >> 2;          // 0..7
    const int tig = lane & 3;           // 0..3
    const int rowBase = (warp & 1) * 32;
    const int colBase = (warp >> 1) * 48;

    float acc[12][4];                   // [mi*6+nt][4]
    #pragma unroll
    for (int i = 0; i < 12; i++)
        #pragma unroll
        for (int j = 0; j < 4; j++) acc[i][j] = 0.f;

    const unsigned* ar0 = infou + (rowBase + gid) * E2_PAD;        // mi=0 rows g/g+8
    const unsigned* ar1 = infou + (rowBase + 16 + gid) * E2_PAD;   // mi=1 rows

    for (int k0 = 0; k0 < 320; k0 += 32) {
        __syncthreads();
        // stage 16 kpairs x 192 cols of weights as bf16x2 (k, k+1 packed)
        #pragma unroll
        for (int i = 0; i < 12; i++) {
            int idx = i * 256 + tid;
            int kp = idx / 192;
            int c = idx - kp * 192;
            int kr = k0 + 2 * kp;
            float f0, f1;
            if (c < 128) {
                f0 = Wne[(size_t)kr * 128 + c];
                f1 = Wne[(size_t)(kr + 1) * 128 + c];
            } else {
                f0 = Wes[(size_t)kr * 64 + (c - 128)];
                f1 = Wes[(size_t)(kr + 1) * 64 + (c - 128)];
            }
            wtu[kp * E2_WPAD + c] = bf16x2(f0, f1);
        }
        __syncthreads();
        #pragma unroll
        for (int ks = 0; ks < 2; ks++) {
            int kw0 = (k0 >> 1) + ks * 8;   // word offset of this k16 group
            unsigned a00 = ar0[kw0 + tig];
            unsigned a01 = ar0[kw0 + tig + 8 * E2_PAD];
            unsigned a02 = ar0[kw0 + tig + 4];
            unsigned a03 = ar0[kw0 + tig + 4 + 8 * E2_PAD];
            unsigned a10 = ar1[kw0 + tig];
            unsigned a11 = ar1[kw0 + tig + 8 * E2_PAD];
            unsigned a12 = ar1[kw0 + tig + 4];
            unsigned a13 = ar1[kw0 + tig + 4 + 8 * E2_PAD];
            const unsigned* bp  = wtu + (ks * 8 + tig) * E2_WPAD + colBase + gid;
            const unsigned* bp4 = bp + 4 * E2_WPAD;
            #pragma unroll
            for (int nt = 0; nt < 6; nt++) {
                unsigned b0 = bp[nt * 8];
                unsigned b1 = bp4[nt * 8];
                mma_bf16(acc[nt],     a00, a01, a02, a03, b0, b1);
                mma_bf16(acc[6 + nt], a10, a11, a12, a13, b0, b1);
            }
        }
    }

    // epilogue: rows eg0 = e0+rowBase+mi*16+gid, eg1 = eg0+8; col c = colBase+nt*8+2*tig
    #pragma unroll
    for (int mi = 0; mi < 2; mi++) {
        const int eg0 = e0 + rowBase + mi * 16 + gid;
        const int eg1 = eg0 + 8;
        const float sw0 = sw[eg0];
        const float sw1 = sw[eg1];
        #pragma unroll
        for (int nt = 0; nt < 6; nt++) {
            const float* av = acc[mi * 6 + nt];
            int c = colBase + nt * 8 + 2 * tig;
            if (c < 128) {
                float bb0 = bne[c], bb1 = bne[c + 1];
                float2 o0, o1;
                o0.x = silu_f(av[0] + bb0) * sw0;
                o0.y = silu_f(av[1] + bb1) * sw0;
                o1.x = silu_f(av[2] + bb0) * sw1;
                o1.y = silu_f(av[3] + bb1) * sw1;
                *(float2*)&g_edge_upd[(size_t)eg0 * 128 + c] = o0;
                *(float2*)&g_edge_upd[(size_t)eg1 * 128 + c] = o1;
            } else {
                int cc = c - 128;
                float bb0 = bes[cc], bb1 = bes[cc + 1];
                float rr0 = eres0[cc], rr1 = eres0[cc + 1];
                float2 base0 = *(const float2*)&edge_ebd[(size_t)eg0 * 64 + cc];
                float2 base1 = *(const float2*)&edge_ebd[(size_t)eg1 * 64 + cc];
                float2 o0, o1;
                o0.x = base0.x + rr0 * silu_f(av[0] + bb0);
                o0.y = base0.y + rr1 * silu_f(av[1] + bb1);
                o1.x = base1.x + rr0 * silu_f(av[2] + bb0);
                o1.y = base1.y + rr1 * silu_f(av[3] + bb1);
                *(float2*)&e_out[(size_t)eg0 * 64 + cc] = o0;
                *(float2*)&e_out[(size_t)eg1 * 64 + cc] = o1;
            }
        }
    }
}

// ================= angle kernel: bf16 MMA dual GEMM =================
// M=64 angles/block, N=96 (0..63 -> W_edge_angle1, 64..95 -> W_angle_self), K=288.
// 8 warps: rowBase=(warp&1)*32, colBase=(warp>>1)*24 -> 2 m16-tiles x 3 n8-tiles.
#define A2_PAD 148   // 148 % 32 == 20 -> banks gid*20+tig all distinct (gcd(20,32)=4, 8 groups*4) OK
#define A2_WPAD 104  // 104 % 32 == 8 -> conflict-free
__global__ void __launch_bounds__(256, 4) k_angle(
    const float* __restrict__ angle_ebd, const float* __restrict__ node_ext,
    const float* __restrict__ edge_ebd, const float* __restrict__ a_sw,
    const int* __restrict__ n2a, const int* __restrict__ eij2a, const int* __restrict__ eik2a,
    const float* __restrict__ W1, const float* __restrict__ b1,
    const float* __restrict__ Wa, const float* __restrict__ ba,
    const float* __restrict__ ares0, float* __restrict__ a_out)
{
    extern __shared__ unsigned smu[];
    unsigned* infou = smu;                       // [64][A2_PAD]
    unsigned* wtu   = smu + 64 * A2_PAD;         // [16][A2_WPAD]
    const int tid = threadIdx.x;
    const int lane = tid & 31;
    const int warp = tid >> 5;
    const int a0g = blockIdx.x * 64;

    // gather angle_info = [angle(32) | node(128) | edge_ik(64) | edge_ij(64)] -> bf16x2
    #pragma unroll
    for (int i = 0; i < 8; i++) {
        int al = warp * 8 + i;
        int ang = a0g + al;
        const float4* pa  = (const float4*)(angle_ebd + (size_t)ang * ADIM);
        const float4* pn  = (const float4*)(node_ext + (size_t)n2a[ang] * NDIM);
        const float4* pik = (const float4*)(edge_ebd + (size_t)eik2a[ang] * EDIM);
        const float4* pij = (const float4*)(edge_ebd + (size_t)eij2a[ang] * EDIM);
        for (int c = lane; c < 72; c += 32) {
            float4 v;
            if (c < 8)       v = pa[c];
            else if (c < 40) v = pn[c - 8];
            else if (c < 56) v = pik[c - 40];
            else             v = pij[c - 56];
            uint2 u;
            u.x = bf16x2(v.x, v.y);
            u.y = bf16x2(v.z, v.w);
            *(uint2*)(infou + al * A2_PAD + c * 2) = u;
        }
    }

    const int gid = lane >> 2;
    const int tig = lane & 3;
    const int rowBase = (warp & 1) * 32;
    const int colBase = (warp >> 1) * 24;

    float acc[6][4];                    // [mi*3+nt][4]
    #pragma unroll
    for (int i = 0; i < 6; i++)
        #pragma unroll
        for (int j = 0; j < 4; j++) acc[i][j] = 0.f;

    const unsigned* ar0 = infou + (rowBase + gid) * A2_PAD;
    const unsigned* ar1 = infou + (rowBase + 16 + gid) * A2_PAD;

    for (int k0 = 0; k0 < 288; k0 += 32) {
        __syncthreads();
        // stage 16 kpairs x 96 cols
        #pragma unroll
        for (int i = 0; i < 6; i++) {
            int idx = i * 256 + tid;
            int kp = idx / 96;
            int c = idx - kp * 96;
            int kr = k0 + 2 * kp;
            float f0, f1;
            if (c < 64) {
                f0 = W1[(size_t)kr * 64 + c];
                f1 = W1[(size_t)(kr + 1) * 64 + c];
            } else {
                f0 = Wa[(size_t)kr * 32 + (c - 64)];
                f1 = Wa[(size_t)(kr + 1) * 32 + (c - 64)];
            }
            wtu[kp * A2_WPAD + c] = bf16x2(f0, f1);
        }
        __syncthreads();
        #pragma unroll
        for (int ks = 0; ks < 2; ks++) {
            int kw0 = (k0 >> 1) + ks * 8;
            unsigned a00 = ar0[kw0 + tig];
            unsigned a01 = ar0[kw0 + tig + 8 * A2_PAD];
            unsigned a02 = ar0[kw0 + tig + 4];
            unsigned a03 = ar0[kw0 + tig + 4 + 8 * A2_PAD];
            unsigned a10 = ar1[kw0 + tig];
            unsigned a11 = ar1[kw0 + tig + 8 * A2_PAD];
            unsigned a12 = ar1[kw0 + tig + 4];
            unsigned a13 = ar1[kw0 + tig + 4 + 8 * A2_PAD];
            const unsigned* bp  = wtu + (ks * 8 + tig) * A2_WPAD + colBase + gid;
            const unsigned* bp4 = bp + 4 * A2_WPAD;
            #pragma unroll
            for (int nt = 0; nt < 3; nt++) {
                unsigned b0 = bp[nt * 8];
                unsigned b1 = bp4[nt * 8];
                mma_bf16(acc[nt],     a00, a01, a02, a03, b0, b1);
                mma_bf16(acc[3 + nt], a10, a11, a12, a13, b0, b1);
            }
        }
    }

    // epilogue
    #pragma unroll
    for (int mi = 0; mi < 2; mi++) {
        const int ag0 = a0g + rowBase + mi * 16 + gid;
        const int ag1 = ag0 + 8;
        const float s0 = a_sw[ag0];
        const float s1 = a_sw[ag1];
        const int e0i = eij2a[ag0];
        const int e1i = eij2a[ag1];
        #pragma unroll
        for (int nt = 0; nt < 3; nt++) {
            const float* av = acc[mi * 3 + nt];
            int c = colBase + nt * 8 + 2 * tig;
            if (c < 64) {
                float bb0 = b1[c], bb1 = b1[c + 1];
                atomicAdd(&g_reduced[(size_t)e0i * 64 + c],     silu_f(av[0] + bb0) * s0);
                atomicAdd(&g_reduced[(size_t)e0i * 64 + c + 1], silu_f(av[1] + bb1) * s0);
                atomicAdd(&g_reduced[(size_t)e1i * 64 + c],     silu_f(av[2] + bb0) * s1);
                atomicAdd(&g_reduced[(size_t)e1i * 64 + c + 1], silu_f(av[3] + bb1) * s1);
            } else {
                int cc = c - 64;
                float bb0 = ba[cc], bb1 = ba[cc + 1];
                float rr0 = ares0[cc], rr1 = ares0[cc + 1];
                float2 base0 = *(const float2*)&angle_ebd[(size_t)ag0 * 32 + cc];
                float2 base1 = *(const float2*)&angle_ebd[(size_t)ag1 * 32 + cc];
                float2 o0, o1;
                o0.x = base0.x + rr0 * silu_f(av[0] + bb0);
                o0.y = base0.y + rr1 * silu_f(av[1] + bb1);
                o1.x = base1.x + rr0 * silu_f(av[2] + bb0);
                o1.y = base1.y + rr1 * silu_f(av[3] + bb1);
                *(float2*)&a_out[(size_t)ag0 * 32 + cc] = o0;
                *(float2*)&a_out[(size_t)ag1 * 32 + cc] = o1;
            }
        }
    }
}

// ================= node kernel: 4 nodes/block in PARALLEL (512 threads) =================
__global__ void __launch_bounds__(512) k_node(
    const float* __restrict__ node_ext, const float* __restrict__ edge_ebd,
    const float* __restrict__ sw, const float* __restrict__ h2,
    const int* __restrict__ nx2e,
    const float* __restrict__ Wns, const float* __restrict__ bns,
    const float* __restrict__ Wsym, const float* __restrict__ bsym,
    const float* __restrict__ nr0, const float* __restrict__ nr1, const float* __restrict__ nr2,
    float* __restrict__ n_out)
{
    __shared__ float s_hn[4][3][128];
    __shared__ float s_he[4][3][64];
    __shared__ float s_sym[4][768];
    __shared__ float s_node[4][128];
    __shared__ float s_msg[4][128];
    __shared__ float s_pS[4][4][128];   // [quarter][node][col]
    __shared__ float s_pY[4][4][128];

    const int nb = blockIdx.x * 4;
    const int t = threadIdx.x;
    const int g = t >> 7;        // node group 0..3
    const int tl = t & 127;      // dim/col 0..127
    const float sc = rsqrtf(6.4f);

    // ---- gather phase: each 128-thread group walks its own node's CSR list ----
    {
        const int n = nb + g;
        const int beg = g_off[n], end = g_off[n + 1];

        float hn0 = 0.f, hn1 = 0.f, hn2 = 0.f;
        float he0 = 0.f, he1 = 0.f, he2 = 0.f;
        float msg = 0.f;
        float nodev = node_ext[(size_t)n * 128 + tl];
        s_node[g][tl] = nodev;

        int e_cur = (beg < end) ? g_ebn[beg] : 0;
        int nx_cur = (beg < end) ? nx2e[e_cur] : 0;
        for (int idx = beg; idx < end; idx++) {
            int e = e_cur, nx = nx_cur;
            if (idx + 1 < end) {
                e_cur = g_ebn[idx + 1];
                nx_cur = nx2e[e_cur];
            }
            float swv = sw[e];
            float hx = h2[e * 3 + 0] * swv;
            float hy = h2[e * 3 + 1] * swv;
            float hz = h2[e * 3 + 2] * swv;
            float nv = node_ext[(size_t)nx * 128 + tl];
            float mv = g_edge_upd[(size_t)e * 128 + tl];
            hn0 += hx * nv; hn1 += hy * nv; hn2 += hz * nv;
            msg += mv;
            if (tl < 64) {
                float ev = edge_ebd[(size_t)e * 64 + tl];
                he0 += hx * ev; he1 += hy * ev; he2 += hz * ev;
            }
        }

        s_hn[g][0][tl] = hn0 * sc; s_hn[g][1][tl] = hn1 * sc; s_hn[g][2][tl] = hn2 * sc;
        if (tl < 64) { s_he[g][0][tl] = he0 * sc; s_he[g][1][tl] = he1 * sc; s_he[g][2][tl] = he2 * sc; }
        s_msg[g][tl] = msg;
    }
    __syncthreads();

    // ---- sym: group g builds node g's 768-dim sym vector ----
    #pragma unroll
    for (int a = 0; a < 4; a++) {
        if (tl < 64)
            s_sym[g][a * 64 + tl] = (s_he[g][0][a] * s_he[g][0][tl] + s_he[g][1][a] * s_he[g][1][tl] +
                                     s_he[g][2][a] * s_he[g][2][tl]) * (1.f / 3.f);
        s_sym[g][256 + a * 128 + tl] = (s_hn[g][0][a] * s_hn[g][0][tl] + s_hn[g][1][a] * s_hn[g][1][tl] +
                                        s_hn[g][2][a] * s_hn[g][2][tl]) * (1.f / 3.f);
    }
    __syncthreads();

    // ---- split-K GEMMs: quarter q = g, col c = tl; partials for all 4 nodes ----
    {
        const int q = g, c = tl;
        float pS[4] = {0.f, 0.f, 0.f, 0.f};
        float pY[4] = {0.f, 0.f, 0.f, 0.f};

        #pragma unroll 4
        for (int k = q * 32; k < q * 32 + 32; k++) {
            float w = Wns[(size_t)k * 128 + c];
            #pragma unroll
            for (int nn = 0; nn < 4; nn++) pS[nn] += s_node[nn][k] * w;
        }
        #pragma unroll 4
        for (int k = q * 192; k < q * 192 + 192; k++) {
            float w = Wsym[(size_t)k * 128 + c];
            #pragma unroll
            for (int nn = 0; nn < 4; nn++) pY[nn] += s_sym[nn][k] * w;
        }
        #pragma unroll
        for (int nn = 0; nn < 4; nn++) {
            s_pS[q][nn][c] = pS[nn];
            s_pY[q][nn][c] = pY[nn];
        }
    }
    __syncthreads();

    // ---- reduce + epilogue: node nn = g, col c = tl ----
    {
        const int nn = g, c = tl;
        float accS = s_pS[0][nn][c] + s_pS[1][nn][c] + s_pS[2][nn][c] + s_pS[3][nn][c];
        float accY = s_pY[0][nn][c] + s_pY[1][nn][c] + s_pY[2][nn][c] + s_pY[3][nn][c];
        float out = s_node[nn][c]
                  + nr0[c] * silu_f(accS + bns[c])
                  + nr1[c] * silu_f(accY + bsym[c])
                  + nr2[c] * (s_msg[nn][c] * (1.f / 6.4f));
        n_out[(size_t)(nb + nn) * 128 + c] = out;
    }
}

// ================= edge2 kernel: reduced(64) @ W_edge_angle2(64x64) =================
__global__ void __launch_bounds__(256) k_edge2(
    const float* __restrict__ W2, const float* __restrict__ b2,
    const float* __restrict__ eres1, float* __restrict__ e_out)
{
    __shared__ float w2s[64 * 64];
    __shared__ float in2[64 * 65];
    __shared__ float b2s[64];
    const int tid = threadIdx.x;
    const int e0 = blockIdx.x * 64;

    #pragma unroll
    for (int i = 0; i < 16; i++) {
        int idx = i * 256 + tid;
        w2s[idx] = W2[idx];
    }
    if (tid < 64) b2s[tid] = b2[tid];
    #pragma unroll
    for (int i = 0; i < 16; i++) {
        int idx = i * 256 + tid;
        int e = idx >> 6, k = idx & 63;
        in2[e * 65 + k] = g_reduced[(size_t)(e0 + e) * 64 + k];
    }
    __syncthreads();

    const int tx = tid & 15, ty = tid >> 4;
    float acc[4][4];
    #pragma unroll
    for (int i = 0; i < 4; i++)
        #pragma unroll
        for (int j = 0; j < 4; j++) acc[i][j] = 0.f;

    #pragma unroll 4
    for (int k = 0; k < 64; k++) {
        float4 wv = *(const float4*)&w2s[k * 64 + tx * 4];
        float w[4] = { wv.x, wv.y, wv.z, wv.w };
        #pragma unroll
        for (int i = 0; i < 4; i++) {
            float a = in2[(ty * 4 + i) * 65 + k];
            #pragma unroll
            for (int j = 0; j < 4; j++) acc[i][j] += a * w[j];
        }
    }

    #pragma unroll
    for (int i = 0; i < 4; i++) {
        int e = e0 + ty * 4 + i;
        #pragma unroll
        for (int j = 0; j < 4; j++) {
            int c = tx * 4 + j;
            float y = silu_f(acc[i][j] + b2s[c]);
            e_out[(size_t)e * 64 + c] += eres1[c] * y;
        }
    }
}

// ---------------- launch ----------------
extern "C" void kernel_launch(void* const* d_in, const int* in_sizes, int n_in,
                              void* d_out, int out_size)
{
    const float* node_ext  = (const float*)d_in[0];
    const float* edge_ebd  = (const float*)d_in[1];
    const float* h2        = (const float*)d_in[2];
    const float* angle_ebd = (const float*)d_in[3];
    const float* sw        = (const float*)d_in[6];
    const float* a_sw      = (const float*)d_in[9];
    const int*   edge_index  = (const int*)d_in[10];
    const int*   angle_index = (const int*)d_in[11];
    const int* n2e   = edge_index;
    const int* nx2e  = edge_index + NEDGE;
    const int* n2a   = angle_index;
    const int* eij2a = angle_index + NANGLE;
    const int* eik2a = angle_index + 2 * NANGLE;

    const float* Wns  = (const float*)d_in[12];
    const float* bns  = (const float*)d_in[13];
    const float* Wsym = (const float*)d_in[14];
    const float* bsym = (const float*)d_in[15];
    const float* Wne  = (const float*)d_in[16];
    const float* bne  = (const float*)d_in[17];
    const float* Wes  = (const float*)d_in[18];
    const float* bes  = (const float*)d_in[19];
    const float* W1   = (const float*)d_in[20];
    const float* b1   = (const float*)d_in[21];
    const float* W2   = (const float*)d_in[22];
    const float* b2   = (const float*)d_in[23];
    const float* Wa   = (const float*)d_in[24];
    const float* ba   = (const float*)d_in[25];
    const float* nr0  = (const float*)d_in[26];
    const float* nr1  = (const float*)d_in[27];
    const float* nr2  = (const float*)d_in[28];
    const float* er0  = (const float*)d_in[29];
    const float* er1  = (const float*)d_in[30];
    const float* ar0  = (const float*)d_in[31];

    float* out   = (float*)d_out;
    float* n_out = out;
    float* e_out = out + (size_t)NLOC * NDIM;
    float* a_out = out + (size_t)NLOC * NDIM + (size_t)NEDGE * EDIM;

    const int edge_smem  = (64 * E2_PAD + 16 * E2_WPAD) * 4;   // 54784 B
    const int angle_smem = (64 * A2_PAD + 16 * A2_WPAD) * 4;   // 44544 B
    cudaFuncSetAttribute(k_edge,  cudaFuncAttributeMaxDynamicSharedMemorySize, edge_smem);
    cudaFuncSetAttribute(k_angle, cudaFuncAttributeMaxDynamicSharedMemorySize, angle_smem);

    // k_edge kept at launch index 3 for ncu capture targeting
    k_zero<<<2048, 256>>>();
    k_hist<<<NEDGE / 256, 256>>>(n2e);
    k_scan<<<1, 1024>>>();
    k_edge<<<NEDGE / 64, 256, edge_smem>>>(node_ext, edge_ebd, sw, n2e, nx2e,
                                           Wne, bne, Wes, bes, er0, e_out);
    k_scatter<<<NEDGE / 256, 256>>>(n2e);
    k_node<<<NLOC / 4, 512>>>(node_ext, edge_ebd, sw, h2, nx2e,
                              Wns, bns, Wsym, bsym, nr0, nr1, nr2, n_out);
    k_angle<<<NANGLE / 64, 256, angle_smem>>>(angle_ebd, node_ext, edge_ebd, a_sw,
                                              n2a, eij2a, eik2a,
                                              W1, b1, Wa, ba, ar0, a_out);
    k_edge2<<<NEDGE / 64, 256>>>(W2, b2, er1, e_out);
}